// round 5
// baseline (speedup 1.0000x reference)
#include <cuda_runtime.h>

#define NN   100000
#define EE   3200000
#define FIN  300
#define HID  16
#define NC   10
#define S2   12                 // padded row stride for 10-wide layer-2 tensors
#define SCAN_BLK 512
#define NB1  ((NN + SCAN_BLK - 1) / SCAN_BLK)   // 196

// ---------------- scratch (device globals: no allocations allowed) ----------
__device__ int   g_is64;
__device__ __align__(16) float g_deg   [NN];
__device__ __align__(16) float g_dinv  [NN];
__device__ __align__(16) int   g_cnt   [NN];
__device__ __align__(16) int   g_start [NN + 1];
__device__ __align__(16) int   g_cursor[NN];
__device__ __align__(16) int   g_bsum  [NB1];
__device__ __align__(16) int   g_boff  [NB1];
__device__ __align__(16) int   g_src   [EE];
__device__ __align__(16) float g_nrm   [EE];
__device__ __align__(16) float g_h1    [NN * HID];
__device__ __align__(16) float g_agg1  [NN * HID];
__device__ __align__(16) float g_h2    [NN * S2];
__device__ __align__(16) float g_agg2  [NN * S2];

// ---------------- edge-index dtype detection (int64 vs int32) ----------------
__global__ void k_detect(const void* __restrict__ ei) {
    if (threadIdx.x == 0 && blockIdx.x == 0) {
        const unsigned long long* p = (const unsigned long long*)ei;
        int ok64 = 1;
        for (int k = 0; k < 64; k++) {
            if (p[k] >= (unsigned long long)NN) { ok64 = 0; break; }
        }
        g_is64 = ok64;
    }
}

__device__ __forceinline__ void load_edge(const void* __restrict__ ei, int e,
                                          int& row, int& col) {
    if (g_is64) {
        const long long* p = (const long long*)ei;
        row = (int)p[e];
        col = (int)p[EE + e];
    } else {
        const int* p = (const int*)ei;
        row = p[e];
        col = p[EE + e];
    }
}

// ---------------- init + weighted degree + edge count ------------------------
__global__ void k_init() {
    int i = blockIdx.x * blockDim.x + threadIdx.x;
    if (i < NN) { g_deg[i] = 1.0f; g_cnt[i] = 0; }   // self-loop weight pre-added
}

__global__ void k_deg_count(const void* __restrict__ ei,
                            const float* __restrict__ w) {
    int e = blockIdx.x * blockDim.x + threadIdx.x;
    if (e < EE) {
        int row, col;
        load_edge(ei, e, row, col);
        atomicAdd(&g_deg[col], w[e]);
        atomicAdd(&g_cnt[col], 1);
    }
}

__global__ void k_dinv() {
    int i = blockIdx.x * blockDim.x + threadIdx.x;
    if (i < NN) g_dinv[i] = rsqrtf(g_deg[i]);        // deg >= 1 always
}

// ---------------- two-level exclusive scan of g_cnt -> g_start ---------------
__global__ void k_scan1() {                      // grid NB1, block SCAN_BLK
    __shared__ int s[SCAN_BLK];
    int i = blockIdx.x * SCAN_BLK + threadIdx.x;
    int v = (i < NN) ? g_cnt[i] : 0;
    s[threadIdx.x] = v;
    __syncthreads();
    for (int d = 1; d < SCAN_BLK; d <<= 1) {
        int t = (threadIdx.x >= d) ? s[threadIdx.x - d] : 0;
        __syncthreads();
        s[threadIdx.x] += t;
        __syncthreads();
    }
    if (i < NN) g_start[i] = s[threadIdx.x] - v;             // local exclusive
    if (threadIdx.x == SCAN_BLK - 1) g_bsum[blockIdx.x] = s[threadIdx.x];
}

__global__ void k_scan2() {                      // 1 block of 256 (NB1 <= 256)
    __shared__ int s[256];
    int t = threadIdx.x;
    int v = (t < NB1) ? g_bsum[t] : 0;
    s[t] = v;
    __syncthreads();
    for (int d = 1; d < 256; d <<= 1) {
        int tv = (t >= d) ? s[t - d] : 0;
        __syncthreads();
        s[t] += tv;
        __syncthreads();
    }
    if (t < NB1) g_boff[t] = s[t] - v;                       // exclusive
    if (t == 0)  g_start[NN] = EE;
}

__global__ void k_scan3() {
    int i = blockIdx.x * blockDim.x + threadIdx.x;
    if (i < NN) {
        int st = g_start[i] + g_boff[i / SCAN_BLK];
        g_start[i]  = st;
        g_cursor[i] = st;
    }
}

// ---------------- scatter edges into CSC (src index + norm) ------------------
__global__ void k_scatter(const void* __restrict__ ei,
                          const float* __restrict__ w) {
    int e = blockIdx.x * blockDim.x + threadIdx.x;
    if (e >= EE) return;
    int row, col;
    load_edge(ei, e, row, col);
    float norm = g_dinv[row] * w[e] * g_dinv[col];
    int p = atomicAdd(&g_cursor[col], 1);
    g_src[p] = row;
    g_nrm[p] = norm;
}

// ---------------- GEMM1: h1 = x @ W1 (static smem only) ----------------------
#define G1_ROWS 24
#define G1_THREADS 128

__global__ void k_gemm1(const float* __restrict__ x,
                        const float* __restrict__ W1) {
    __shared__ float  sx [G1_ROWS * FIN];    // 28800 B
    __shared__ float4 sw4[FIN * 4];          // 19200 B  (300 x 16 floats)

    int r0   = blockIdx.x * G1_ROWS;
    int rows = min(G1_ROWS, NN - r0);

    const float4* xg  = (const float4*)(x + (size_t)r0 * FIN);
    float4*       sx4 = (float4*)sx;
    int cnt4 = rows * FIN / 4;               // FIN%4==0
    for (int i = threadIdx.x; i < cnt4; i += G1_THREADS) sx4[i] = xg[i];
    const float4* wg = (const float4*)W1;
    for (int i = threadIdx.x; i < FIN * 4; i += G1_THREADS) sw4[i] = wg[i];
    __syncthreads();

    int r = threadIdx.x >> 2;                // row within tile
    int g = threadIdx.x & 3;                 // 4-col group
    if (r < rows) {
        float4 acc = make_float4(0.f, 0.f, 0.f, 0.f);
        const float* xr = sx + r * FIN;
#pragma unroll 4
        for (int k = 0; k < FIN; k++) {
            float  xv = xr[k];
            float4 wv = sw4[k * 4 + g];
            acc.x += xv * wv.x; acc.y += xv * wv.y;
            acc.z += xv * wv.z; acc.w += xv * wv.w;
        }
        ((float4*)g_h1)[(r0 + r) * 4 + g] = acc;
    }
}

// ---------------- conv1 gather: agg1[i] = sum_e h1[src]*nrm + h1[i]*dinv^2 ---
__global__ void k_conv1() {
    int t = blockIdx.x * blockDim.x + threadIdx.x;
    int i = t >> 2;
    int c = t & 3;
    if (i >= NN) return;
    float di = g_dinv[i];
    float d2 = di * di;
    const float4* h14 = (const float4*)g_h1;
    float4 acc = h14[i * 4 + c];
    acc.x *= d2; acc.y *= d2; acc.z *= d2; acc.w *= d2;
    int s  = g_start[i];
    int e1 = g_start[i + 1];
    for (int p = s; p < e1; p++) {
        int   src = g_src[p];
        float nr  = g_nrm[p];
        float4 v = h14[src * 4 + c];
        acc.x += v.x * nr; acc.y += v.y * nr;
        acc.z += v.z * nr; acc.w += v.w * nr;
    }
    ((float4*)g_agg1)[i * 4 + c] = acc;
}

// ---------------- layer2: z=relu(agg1+b1); h2 = z @ W2 -----------------------
__global__ void k_layer2(const float* __restrict__ b1,
                         const float* __restrict__ W2) {
    __shared__ float sW2[HID * NC];
    __shared__ float sb1[HID];
    if (threadIdx.x < HID * NC) sW2[threadIdx.x] = W2[threadIdx.x];
    if (threadIdx.x < HID)      sb1[threadIdx.x] = b1[threadIdx.x];
    __syncthreads();

    int i = blockIdx.x * blockDim.x + threadIdx.x;
    if (i >= NN) return;

    float z[HID];
    const float4* a4 = ((const float4*)g_agg1) + i * 4;
#pragma unroll
    for (int q = 0; q < 4; q++) {
        float4 v = a4[q];
        z[q * 4 + 0] = fmaxf(v.x + sb1[q * 4 + 0], 0.f);
        z[q * 4 + 1] = fmaxf(v.y + sb1[q * 4 + 1], 0.f);
        z[q * 4 + 2] = fmaxf(v.z + sb1[q * 4 + 2], 0.f);
        z[q * 4 + 3] = fmaxf(v.w + sb1[q * 4 + 3], 0.f);
    }
    float h[NC];
#pragma unroll
    for (int cc = 0; cc < NC; cc++) {
        float s = 0.f;
#pragma unroll
        for (int k = 0; k < HID; k++) s += z[k] * sW2[k * NC + cc];
        h[cc] = s;
    }
    float* ph = g_h2 + i * S2;
    *(float4*)(ph + 0) = make_float4(h[0], h[1], h[2], h[3]);
    *(float4*)(ph + 4) = make_float4(h[4], h[5], h[6], h[7]);
    *(float2*)(ph + 8) = make_float2(h[8], h[9]);
}

// ---------------- conv2 gather (S2-padded, chunks {v4,v4,v2}) ----------------
__global__ void k_conv2() {
    int t = blockIdx.x * blockDim.x + threadIdx.x;
    int i = t >> 2;
    int c = t & 3;
    if (i >= NN || c == 3) return;
    float di = g_dinv[i];
    float d2 = di * di;
    int s  = g_start[i];
    int e1 = g_start[i + 1];
    if (c < 2) {
        const float* base = g_h2 + c * 4;
        float4 acc = *(const float4*)(base + i * S2);
        acc.x *= d2; acc.y *= d2; acc.z *= d2; acc.w *= d2;
        for (int p = s; p < e1; p++) {
            int   src = g_src[p];
            float nr  = g_nrm[p];
            float4 v = *(const float4*)(base + src * S2);
            acc.x += v.x * nr; acc.y += v.y * nr;
            acc.z += v.z * nr; acc.w += v.w * nr;
        }
        *(float4*)(g_agg2 + i * S2 + c * 4) = acc;
    } else {
        const float* base = g_h2 + 8;
        float2 acc = *(const float2*)(base + i * S2);
        acc.x *= d2; acc.y *= d2;
        for (int p = s; p < e1; p++) {
            int   src = g_src[p];
            float nr  = g_nrm[p];
            float2 v = *(const float2*)(base + src * S2);
            acc.x += v.x * nr; acc.y += v.y * nr;
        }
        *(float2*)(g_agg2 + i * S2 + 8) = acc;
    }
}

// ---------------- log_softmax(agg2 + b2) -------------------------------------
__global__ void k_lsm(const float* __restrict__ b2, float* __restrict__ out) {
    int i = blockIdx.x * blockDim.x + threadIdx.x;
    if (i >= NN) return;
    const float* a = g_agg2 + i * S2;
    float v[NC];
    float m = -1e30f;
#pragma unroll
    for (int c = 0; c < NC; c++) {
        v[c] = a[c] + b2[c];
        m = fmaxf(m, v[c]);
    }
    float s = 0.f;
#pragma unroll
    for (int c = 0; c < NC; c++) s += expf(v[c] - m);
    float l = logf(s);
    float* o = out + i * NC;
#pragma unroll
    for (int c = 0; c < NC; c++) o[c] = v[c] - m - l;
}

// ---------------- launch -----------------------------------------------------
extern "C" void kernel_launch(void* const* d_in, const int* in_sizes, int n_in,
                              void* d_out, int out_size) {
    const float* x   = (const float*)d_in[0];
    const void*  ei  = d_in[1];
    const float* w   = (const float*)d_in[2];
    const float* W1  = (const float*)d_in[3];
    const float* b1  = (const float*)d_in[4];
    const float* W2  = (const float*)d_in[5];
    const float* b2  = (const float*)d_in[6];
    float*       out = (float*)d_out;

    k_detect    <<<1, 32>>>(ei);
    k_init      <<<(NN + 255) / 256, 256>>>();
    k_deg_count <<<(EE + 255) / 256, 256>>>(ei, w);
    k_dinv      <<<(NN + 255) / 256, 256>>>();
    k_scan1     <<<NB1, SCAN_BLK>>>();
    k_scan2     <<<1, 256>>>();
    k_scan3     <<<(NN + 255) / 256, 256>>>();
    k_scatter   <<<(EE + 255) / 256, 256>>>(ei, w);
    k_gemm1     <<<(NN + G1_ROWS - 1) / G1_ROWS, G1_THREADS>>>(x, W1);
    k_conv1     <<<(NN * 4 + 255) / 256, 256>>>();
    k_layer2    <<<(NN + 255) / 256, 256>>>(b1, W2);
    k_conv2     <<<(NN * 4 + 255) / 256, 256>>>();
    k_lsm       <<<(NN + 255) / 256, 256>>>(b2, out);
}

// round 6
// speedup vs baseline: 1.1003x; 1.1003x over previous
#include <cuda_runtime.h>

#define NN   100000
#define EE   3200000
#define FIN  300
#define HID  16
#define NC   10
#define S2   12                 // padded row stride for h2
#define SCAN_BLK 512
#define NB1  ((NN + SCAN_BLK - 1) / SCAN_BLK)   // 196

// ---------------- scratch (device globals: no allocations allowed) ----------
__device__ int   g_is64;
__device__ __align__(16) float g_deg   [NN];
__device__ __align__(16) float g_dinv  [NN];
__device__ __align__(16) int   g_cnt   [NN];
__device__ __align__(16) int   g_start [NN + 1];
__device__ __align__(16) int   g_cursor[NN];
__device__ __align__(16) int   g_bsum  [NB1];
__device__ __align__(16) int   g_boff  [NB1];
__device__ __align__(16) int2  g_edge  [EE];      // packed (src, norm-bits)
__device__ __align__(16) float g_h1    [NN * HID];
__device__ __align__(16) float g_h2    [NN * S2];

// ---------------- init (+ edge dtype detect in thread 0) ---------------------
__global__ void k_init(const void* __restrict__ ei) {
    int i = blockIdx.x * blockDim.x + threadIdx.x;
    if (i < NN) { g_deg[i] = 1.0f; g_cnt[i] = 0; }   // self-loop pre-added
    if (i == 0) {
        const unsigned long long* p = (const unsigned long long*)ei;
        int ok64 = 1;
        for (int k = 0; k < 64; k++)
            if (p[k] >= (unsigned long long)NN) { ok64 = 0; break; }
        g_is64 = ok64;
    }
}

// ---------------- weighted degree + edge count (col only) --------------------
__global__ void k_deg_count(const void* __restrict__ ei,
                            const float* __restrict__ w) {
    int e = blockIdx.x * blockDim.x + threadIdx.x;
    if (e >= EE) return;
    int col;
    if (g_is64) col = (int)((const long long*)ei)[EE + e];
    else        col = ((const int*)ei)[EE + e];
    atomicAdd(&g_deg[col], w[e]);
    atomicAdd(&g_cnt[col], 1);
}

// ---------------- scan level 1 (+ dinv) --------------------------------------
__global__ void k_scan1() {
    __shared__ int s[SCAN_BLK];
    int i = blockIdx.x * SCAN_BLK + threadIdx.x;
    int v = (i < NN) ? g_cnt[i] : 0;
    s[threadIdx.x] = v;
    __syncthreads();
    for (int d = 1; d < SCAN_BLK; d <<= 1) {
        int t = (threadIdx.x >= d) ? s[threadIdx.x - d] : 0;
        __syncthreads();
        s[threadIdx.x] += t;
        __syncthreads();
    }
    if (i < NN) {
        g_start[i] = s[threadIdx.x] - v;             // local exclusive
        g_dinv[i]  = rsqrtf(g_deg[i]);               // deg >= 1 always
    }
    if (threadIdx.x == SCAN_BLK - 1) g_bsum[blockIdx.x] = s[threadIdx.x];
}

__global__ void k_scan2() {                          // 1 block (NB1 <= 256)
    __shared__ int s[256];
    int t = threadIdx.x;
    int v = (t < NB1) ? g_bsum[t] : 0;
    s[t] = v;
    __syncthreads();
    for (int d = 1; d < 256; d <<= 1) {
        int tv = (t >= d) ? s[t - d] : 0;
        __syncthreads();
        s[t] += tv;
        __syncthreads();
    }
    if (t < NB1) g_boff[t] = s[t] - v;
    if (t == 0)  g_start[NN] = EE;
}

__global__ void k_scan3() {
    int i = blockIdx.x * blockDim.x + threadIdx.x;
    if (i < NN) {
        int st = g_start[i] + g_boff[i / SCAN_BLK];
        g_start[i]  = st;
        g_cursor[i] = st;
    }
}

// ---------------- scatter edges into CSC (packed 8B payload) -----------------
__global__ void k_scatter(const void* __restrict__ ei,
                          const float* __restrict__ w) {
    int e = blockIdx.x * blockDim.x + threadIdx.x;
    if (e >= EE) return;
    int row, col;
    if (g_is64) {
        const long long* p = (const long long*)ei;
        row = (int)p[e]; col = (int)p[EE + e];
    } else {
        const int* p = (const int*)ei;
        row = p[e]; col = p[EE + e];
    }
    float norm = g_dinv[row] * w[e] * g_dinv[col];
    int p = atomicAdd(&g_cursor[col], 1);
    g_edge[p] = make_int2(row, __float_as_int(norm));
}

// ---------------- GEMM1: h1 = x @ W1 (96 thr, all compute lanes live) --------
#define G1_ROWS 24
#define G1_THREADS 96

__global__ void k_gemm1(const float* __restrict__ x,
                        const float* __restrict__ W1) {
    __shared__ float  sx [G1_ROWS * FIN];    // 28800 B
    __shared__ float4 sw4[FIN * 4];          // 19200 B

    int r0   = blockIdx.x * G1_ROWS;
    int rows = min(G1_ROWS, NN - r0);

    const float4* xg  = (const float4*)(x + (size_t)r0 * FIN);
    float4*       sx4 = (float4*)sx;
    int cnt4 = rows * FIN / 4;
    for (int i = threadIdx.x; i < cnt4; i += G1_THREADS) sx4[i] = xg[i];
    const float4* wg = (const float4*)W1;
    for (int i = threadIdx.x; i < FIN * 4; i += G1_THREADS) sw4[i] = wg[i];
    __syncthreads();

    int r = threadIdx.x >> 2;                // 0..23, always valid vs G1_ROWS
    int g = threadIdx.x & 3;
    if (r < rows) {
        float4 acc = make_float4(0.f, 0.f, 0.f, 0.f);
        const float* xr = sx + r * FIN;
#pragma unroll 4
        for (int k = 0; k < FIN; k++) {
            float  xv = xr[k];
            float4 wv = sw4[k * 4 + g];
            acc.x += xv * wv.x; acc.y += xv * wv.y;
            acc.z += xv * wv.z; acc.w += xv * wv.w;
        }
        ((float4*)g_h1)[(r0 + r) * 4 + g] = acc;
    }
}

// ---------------- conv1 + bias + relu + GEMM2 fused --------------------------
// 4 threads per node; thread c owns float4 chunk c of the 16-wide feature.
__global__ void k_conv1f(const float* __restrict__ b1,
                         const float* __restrict__ W2) {
    __shared__ float sW2[HID * NC];
    __shared__ float sb1[HID];
    if (threadIdx.x < HID * NC) sW2[threadIdx.x] = W2[threadIdx.x];
    if (threadIdx.x < HID)      sb1[threadIdx.x] = b1[threadIdx.x];
    __syncthreads();

    int t = blockIdx.x * blockDim.x + threadIdx.x;
    int i = t >> 2;
    int c = t & 3;
    if (i >= NN) return;

    float di = g_dinv[i];
    float d2 = di * di;
    const float4* h14 = (const float4*)g_h1;
    float4 acc = h14[i * 4 + c];
    acc.x *= d2; acc.y *= d2; acc.z *= d2; acc.w *= d2;

    int s  = g_start[i];
    int e1 = g_start[i + 1];
    for (int p = s; p < e1; p++) {
        int2  ed = g_edge[p];
        float nr = __int_as_float(ed.y);
        float4 v = h14[ed.x * 4 + c];
        acc.x += v.x * nr; acc.y += v.y * nr;
        acc.z += v.z * nr; acc.w += v.w * nr;
    }

    // bias + relu on this thread's 4 features
    int k0 = c * 4;
    float z0 = fmaxf(acc.x + sb1[k0 + 0], 0.f);
    float z1 = fmaxf(acc.y + sb1[k0 + 1], 0.f);
    float z2 = fmaxf(acc.z + sb1[k0 + 2], 0.f);
    float z3 = fmaxf(acc.w + sb1[k0 + 3], 0.f);

    // partial 16x10 GEMM using this thread's 4 z entries
    float h[NC];
#pragma unroll
    for (int cc = 0; cc < NC; cc++) {
        h[cc] = z0 * sW2[(k0 + 0) * NC + cc] + z1 * sW2[(k0 + 1) * NC + cc]
              + z2 * sW2[(k0 + 2) * NC + cc] + z3 * sW2[(k0 + 3) * NC + cc];
    }
    // butterfly-sum across the 4-lane group (all 4 lanes of a live group are active)
    unsigned gm = 0xFu << ((threadIdx.x & 31) & ~3);
#pragma unroll
    for (int cc = 0; cc < NC; cc++) {
        h[cc] += __shfl_xor_sync(gm, h[cc], 1, 4);
        h[cc] += __shfl_xor_sync(gm, h[cc], 2, 4);
    }
    float* ph = g_h2 + i * S2;
    if (c == 0)      *(float4*)(ph + 0) = make_float4(h[0], h[1], h[2], h[3]);
    else if (c == 1) *(float4*)(ph + 4) = make_float4(h[4], h[5], h[6], h[7]);
    else if (c == 2) *(float2*)(ph + 8) = make_float2(h[8], h[9]);
}

// ---------------- conv2 + bias + log_softmax fused ---------------------------
// thread c: chunk sizes {4,4,2,0}; lane 3 joins the butterfly with -inf/0.
__global__ void k_conv2f(const float* __restrict__ b2,
                         float* __restrict__ out) {
    int t = blockIdx.x * blockDim.x + threadIdx.x;
    int i = t >> 2;
    int c = t & 3;
    if (i >= NN) return;

    int nc = (c < 2) ? 4 : (c == 2 ? 2 : 0);
    float v0 = 0.f, v1 = 0.f, v2 = 0.f, v3 = 0.f;

    if (nc) {
        float di = g_dinv[i];
        float d2 = di * di;
        int s  = g_start[i];
        int e1 = g_start[i + 1];
        const float* basei = g_h2 + i * S2 + c * 4;
        if (nc == 4) {
            float4 a = *(const float4*)basei;
            v0 = a.x * d2; v1 = a.y * d2; v2 = a.z * d2; v3 = a.w * d2;
            for (int p = s; p < e1; p++) {
                int2  ed = g_edge[p];
                float nr = __int_as_float(ed.y);
                float4 hv = *(const float4*)(g_h2 + ed.x * S2 + c * 4);
                v0 += hv.x * nr; v1 += hv.y * nr; v2 += hv.z * nr; v3 += hv.w * nr;
            }
        } else {
            float2 a = *(const float2*)basei;
            v0 = a.x * d2; v1 = a.y * d2;
            for (int p = s; p < e1; p++) {
                int2  ed = g_edge[p];
                float nr = __int_as_float(ed.y);
                float2 hv = *(const float2*)(g_h2 + ed.x * S2 + 8);
                v0 += hv.x * nr; v1 += hv.y * nr;
            }
        }
        // add bias
        v0 += b2[c * 4 + 0];
        if (nc >= 2) v1 += b2[c * 4 + 1];
        if (nc == 4) { v2 += b2[c * 4 + 2]; v3 += b2[c * 4 + 3]; }
    }

    // butterfly max over the 4-lane group
    float m = -1e30f;
    if (nc >= 1) m = fmaxf(m, v0);
    if (nc >= 2) m = fmaxf(m, v1);
    if (nc == 4) m = fmaxf(fmaxf(m, v2), v3);
    unsigned gm = 0xFu << ((threadIdx.x & 31) & ~3);
    m = fmaxf(m, __shfl_xor_sync(gm, m, 1, 4));
    m = fmaxf(m, __shfl_xor_sync(gm, m, 2, 4));

    // butterfly sum of exp
    float sum = 0.f;
    if (nc >= 1) sum += __expf(v0 - m);
    if (nc >= 2) sum += __expf(v1 - m);
    if (nc == 4) sum += __expf(v2 - m) + __expf(v3 - m);
    sum += __shfl_xor_sync(gm, sum, 1, 4);
    sum += __shfl_xor_sync(gm, sum, 2, 4);
    float l = __logf(sum) + m;

    // write (all float2 stores are 8B-aligned: 40*i bytes base)
    float* o = out + i * NC + c * 4;
    if (nc == 4) {
        *(float2*)(o + 0) = make_float2(v0 - l, v1 - l);
        *(float2*)(o + 2) = make_float2(v2 - l, v3 - l);
    } else if (nc == 2) {
        *(float2*)(o + 0) = make_float2(v0 - l, v1 - l);
    }
}

// ---------------- launch -----------------------------------------------------
extern "C" void kernel_launch(void* const* d_in, const int* in_sizes, int n_in,
                              void* d_out, int out_size) {
    const float* x   = (const float*)d_in[0];
    const void*  ei  = d_in[1];
    const float* w   = (const float*)d_in[2];
    const float* W1  = (const float*)d_in[3];
    const float* b1  = (const float*)d_in[4];
    const float* W2  = (const float*)d_in[5];
    const float* b2  = (const float*)d_in[6];
    float*       out = (float*)d_out;

    k_init      <<<(NN + 255) / 256, 256>>>(ei);
    k_deg_count <<<(EE + 255) / 256, 256>>>(ei, w);
    k_scan1     <<<NB1, SCAN_BLK>>>();
    k_scan2     <<<1, 256>>>();
    k_scan3     <<<(NN + 255) / 256, 256>>>();
    k_scatter   <<<(EE + 255) / 256, 256>>>(ei, w);
    k_gemm1     <<<(NN + G1_ROWS - 1) / G1_ROWS, G1_THREADS>>>(x, W1);
    k_conv1f    <<<(NN * 4 + 255) / 256, 256>>>(b1, W2);
    k_conv2f    <<<(NN * 4 + 255) / 256, 256>>>(b2, out);
}

// round 9
// speedup vs baseline: 1.1244x; 1.0218x over previous
#include <cuda_runtime.h>

#define NN   100000
#define EE   3200000
#define FIN  300
#define HID  16
#define NC   10
#define S2   12
#define SCAN_BLK 512
#define NB1  ((NN + SCAN_BLK - 1) / SCAN_BLK)   // 196

// ---------------- scratch (device globals) -----------------------------------
__device__ int   g_is64;
__device__ __align__(16) float g_deg   [NN];
__device__ __align__(16) float g_dinv  [NN];
__device__ __align__(16) int   g_cnt   [NN];
__device__ __align__(16) int   g_start [NN + 1];
__device__ __align__(16) int   g_cursor[NN];
__device__ __align__(16) int   g_bsum  [NB1];
__device__ __align__(16) int2  g_edge  [EE];      // packed (src, norm-bits)
__device__ __align__(16) float g_h1    [NN * HID];
__device__ __align__(16) float g_h2    [NN * S2];

// ---------------- init (+ edge dtype detect) ---------------------------------
__global__ void k_init(const void* __restrict__ ei) {
    int i = blockIdx.x * blockDim.x + threadIdx.x;
    if (i < NN) { g_deg[i] = 1.0f; g_cnt[i] = 0; }
    if (i == 0) {
        const unsigned long long* p = (const unsigned long long*)ei;
        int ok64 = 1;
        for (int k = 0; k < 64; k++)
            if (p[k] >= (unsigned long long)NN) { ok64 = 0; break; }
        g_is64 = ok64;
    }
}

// ---------------- weighted degree + count (4 edges/thread) -------------------
__global__ void k_deg_count(const void* __restrict__ ei,
                            const float* __restrict__ w) {
    int e4 = blockIdx.x * blockDim.x + threadIdx.x;
    if (e4 >= EE / 4) return;
    float4 w4 = ((const float4*)w)[e4];
    if (!g_is64) {
        int4 c4 = ((const int4*)((const int*)ei + EE))[e4];
        atomicAdd(&g_deg[c4.x], w4.x); atomicAdd(&g_cnt[c4.x], 1);
        atomicAdd(&g_deg[c4.y], w4.y); atomicAdd(&g_cnt[c4.y], 1);
        atomicAdd(&g_deg[c4.z], w4.z); atomicAdd(&g_cnt[c4.z], 1);
        atomicAdd(&g_deg[c4.w], w4.w); atomicAdd(&g_cnt[c4.w], 1);
    } else {
        const long long* p = (const long long*)ei + EE + e4 * 4;
        const float* wp = &w4.x;
        for (int k = 0; k < 4; k++) {
            int col = (int)p[k];
            atomicAdd(&g_deg[col], wp[k]); atomicAdd(&g_cnt[col], 1);
        }
    }
}

// ---------------- scan level 1 (+ dinv) --------------------------------------
__global__ void k_scan1() {
    __shared__ int s[SCAN_BLK];
    int i = blockIdx.x * SCAN_BLK + threadIdx.x;
    int v = (i < NN) ? g_cnt[i] : 0;
    s[threadIdx.x] = v;
    __syncthreads();
    for (int d = 1; d < SCAN_BLK; d <<= 1) {
        int t = (threadIdx.x >= d) ? s[threadIdx.x - d] : 0;
        __syncthreads();
        s[threadIdx.x] += t;
        __syncthreads();
    }
    if (i < NN) {
        g_start[i] = s[threadIdx.x] - v;
        g_dinv[i]  = rsqrtf(g_deg[i]);
    }
    if (threadIdx.x == SCAN_BLK - 1) g_bsum[blockIdx.x] = s[threadIdx.x];
}

// ---------------- scan levels 2+3 merged (each block rescans bsums) ----------
__global__ void k_scan23() {
    __shared__ int s[256];
    __shared__ int sexc[256];
    int t = threadIdx.x;
    int v = (t < NB1) ? g_bsum[t] : 0;
    s[t] = v;
    __syncthreads();
    for (int d = 1; d < 256; d <<= 1) {
        int tv = (t >= d) ? s[t - d] : 0;
        __syncthreads();
        s[t] += tv;
        __syncthreads();
    }
    sexc[t] = s[t] - v;                      // exclusive block offset
    __syncthreads();
    int i = blockIdx.x * 256 + t;
    if (i < NN) {
        int st = g_start[i] + sexc[i / SCAN_BLK];
        g_start[i]  = st;
        g_cursor[i] = st;
    }
    if (blockIdx.x == 0 && t == 0) g_start[NN] = EE;
}

// ---------------- scatter edges into CSC -------------------------------------
__global__ void k_scatter(const void* __restrict__ ei,
                          const float* __restrict__ w) {
    int e = blockIdx.x * blockDim.x + threadIdx.x;
    if (e >= EE) return;
    int row, col;
    if (g_is64) {
        const long long* p = (const long long*)ei;
        row = (int)p[e]; col = (int)p[EE + e];
    } else {
        const int* p = (const int*)ei;
        row = p[e]; col = p[EE + e];
    }
    float norm = g_dinv[row] * w[e] * g_dinv[col];
    int p = atomicAdd(&g_cursor[col], 1);
    g_edge[p] = make_int2(row, __float_as_int(norm));
}

// ---------------- GEMM1: h1 = x @ W1 -----------------------------------------
#define G1_ROWS 24
#define G1_THREADS 96

__global__ void k_gemm1(const float* __restrict__ x,
                        const float* __restrict__ W1) {
    __shared__ float  sx [G1_ROWS * FIN];
    __shared__ float4 sw4[FIN * 4];

    int r0   = blockIdx.x * G1_ROWS;
    int rows = min(G1_ROWS, NN - r0);

    const float4* xg  = (const float4*)(x + (size_t)r0 * FIN);
    float4*       sx4 = (float4*)sx;
    int cnt4 = rows * FIN / 4;
    for (int i = threadIdx.x; i < cnt4; i += G1_THREADS) sx4[i] = xg[i];
    const float4* wg = (const float4*)W1;
    for (int i = threadIdx.x; i < FIN * 4; i += G1_THREADS) sw4[i] = wg[i];
    __syncthreads();

    int r = threadIdx.x >> 2;
    int g = threadIdx.x & 3;
    if (r < rows) {
        float4 acc = make_float4(0.f, 0.f, 0.f, 0.f);
        const float* xr = sx + r * FIN;
#pragma unroll 4
        for (int k = 0; k < FIN; k++) {
            float  xv = xr[k];
            float4 wv = sw4[k * 4 + g];
            acc.x += xv * wv.x; acc.y += xv * wv.y;
            acc.z += xv * wv.z; acc.w += xv * wv.w;
        }
        ((float4*)g_h1)[(r0 + r) * 4 + g] = acc;
    }
}

// ---------------- conv1 + bias + relu + GEMM2 fused (8 lanes/node) -----------
// lanes (sub,c): sub in {0,1} processes even/odd edges; c owns float4 chunk c.
__global__ void k_conv1f(const float* __restrict__ b1,
                         const float* __restrict__ W2) {
    __shared__ float sW2[HID * NC];
    __shared__ float sb1[HID];
    if (threadIdx.x < HID * NC) sW2[threadIdx.x] = W2[threadIdx.x];
    if (threadIdx.x < HID)      sb1[threadIdx.x] = b1[threadIdx.x];
    __syncthreads();

    int t = blockIdx.x * blockDim.x + threadIdx.x;   // exact grid: NN*8 threads
    int i   = t >> 3;
    int sub = (t >> 2) & 1;
    int c   = t & 3;

    const float4* h14 = (const float4*)g_h1;
    float4 acc = make_float4(0.f, 0.f, 0.f, 0.f);
    if (sub == 0) {                                  // self-loop term
        float di = g_dinv[i];
        float d2 = di * di;
        acc = h14[i * 4 + c];
        acc.x *= d2; acc.y *= d2; acc.z *= d2; acc.w *= d2;
    }
    int s  = g_start[i];
    int e1 = g_start[i + 1];
    for (int p = s + sub; p < e1; p += 2) {
        int2  ed = g_edge[p];
        float nr = __int_as_float(ed.y);
        float4 v = h14[ed.x * 4 + c];
        acc.x += v.x * nr; acc.y += v.y * nr;
        acc.z += v.z * nr; acc.w += v.w * nr;
    }
    // merge even/odd halves (both halves end with the complete sum)
    acc.x += __shfl_xor_sync(0xFFFFFFFFu, acc.x, 4);
    acc.y += __shfl_xor_sync(0xFFFFFFFFu, acc.y, 4);
    acc.z += __shfl_xor_sync(0xFFFFFFFFu, acc.z, 4);
    acc.w += __shfl_xor_sync(0xFFFFFFFFu, acc.w, 4);

    // bias + relu on chunk c
    int k0 = c * 4;
    float z0 = fmaxf(acc.x + sb1[k0 + 0], 0.f);
    float z1 = fmaxf(acc.y + sb1[k0 + 1], 0.f);
    float z2 = fmaxf(acc.z + sb1[k0 + 2], 0.f);
    float z3 = fmaxf(acc.w + sb1[k0 + 3], 0.f);

    float h[NC];
#pragma unroll
    for (int cc = 0; cc < NC; cc++) {
        h[cc] = z0 * sW2[(k0 + 0) * NC + cc] + z1 * sW2[(k0 + 1) * NC + cc]
              + z2 * sW2[(k0 + 2) * NC + cc] + z3 * sW2[(k0 + 3) * NC + cc];
    }
    // sum the 4 c-chunks within this sub-half
#pragma unroll
    for (int cc = 0; cc < NC; cc++) {
        h[cc] += __shfl_xor_sync(0xFFFFFFFFu, h[cc], 1, 4);
        h[cc] += __shfl_xor_sync(0xFFFFFFFFu, h[cc], 2, 4);
    }
    if (sub == 0) {
        float* ph = g_h2 + i * S2;
        if (c == 0)      *(float4*)(ph + 0) = make_float4(h[0], h[1], h[2], h[3]);
        else if (c == 1) *(float4*)(ph + 4) = make_float4(h[4], h[5], h[6], h[7]);
        else if (c == 2) *(float2*)(ph + 8) = make_float2(h[8], h[9]);
    }
}

// ---------------- conv2 + bias + log_softmax fused (8 lanes/node) ------------
__global__ void k_conv2f(const float* __restrict__ b2,
                         float* __restrict__ out) {
    int t = blockIdx.x * blockDim.x + threadIdx.x;   // exact grid: NN*8 threads
    int i   = t >> 3;
    int sub = (t >> 2) & 1;
    int c   = t & 3;

    int nc = (c < 2) ? 4 : (c == 2 ? 2 : 0);
    float v0 = 0.f, v1 = 0.f, v2 = 0.f, v3 = 0.f;

    if (nc) {
        int s  = g_start[i];
        int e1 = g_start[i + 1];
        if (sub == 0) {                              // self-loop term
            float di = g_dinv[i];
            float d2 = di * di;
            const float* basei = g_h2 + i * S2 + c * 4;
            if (nc == 4) {
                float4 a = *(const float4*)basei;
                v0 = a.x * d2; v1 = a.y * d2; v2 = a.z * d2; v3 = a.w * d2;
            } else {
                float2 a = *(const float2*)basei;
                v0 = a.x * d2; v1 = a.y * d2;
            }
        }
        if (nc == 4) {
            for (int p = s + sub; p < e1; p += 2) {
                int2  ed = g_edge[p];
                float nr = __int_as_float(ed.y);
                float4 hv = *(const float4*)(g_h2 + ed.x * S2 + c * 4);
                v0 += hv.x * nr; v1 += hv.y * nr; v2 += hv.z * nr; v3 += hv.w * nr;
            }
        } else {
            for (int p = s + sub; p < e1; p += 2) {
                int2  ed = g_edge[p];
                float nr = __int_as_float(ed.y);
                float2 hv = *(const float2*)(g_h2 + ed.x * S2 + 8);
                v0 += hv.x * nr; v1 += hv.y * nr;
            }
        }
    }
    // merge halves
    v0 += __shfl_xor_sync(0xFFFFFFFFu, v0, 4);
    v1 += __shfl_xor_sync(0xFFFFFFFFu, v1, 4);
    v2 += __shfl_xor_sync(0xFFFFFFFFu, v2, 4);
    v3 += __shfl_xor_sync(0xFFFFFFFFu, v3, 4);

    if (nc) {
        v0 += b2[c * 4 + 0];
        if (nc >= 2) v1 += b2[c * 4 + 1];
        if (nc == 4) { v2 += b2[c * 4 + 2]; v3 += b2[c * 4 + 3]; }
    }

    float m = -1e30f;
    if (nc >= 1) m = fmaxf(m, v0);
    if (nc >= 2) m = fmaxf(m, v1);
    if (nc == 4) m = fmaxf(fmaxf(m, v2), v3);
    m = fmaxf(m, __shfl_xor_sync(0xFFFFFFFFu, m, 1, 4));
    m = fmaxf(m, __shfl_xor_sync(0xFFFFFFFFu, m, 2, 4));

    float sum = 0.f;
    if (nc >= 1) sum += __expf(v0 - m);
    if (nc >= 2) sum += __expf(v1 - m);
    if (nc == 4) sum += __expf(v2 - m) + __expf(v3 - m);
    sum += __shfl_xor_sync(0xFFFFFFFFu, sum, 1, 4);
    sum += __shfl_xor_sync(0xFFFFFFFFu, sum, 2, 4);
    float l = __logf(sum) + m;

    if (sub == 0 && nc) {
        float* o = out + i * NC + c * 4;
        if (nc == 4) {
            *(float2*)(o + 0) = make_float2(v0 - l, v1 - l);
            *(float2*)(o + 2) = make_float2(v2 - l, v3 - l);
        } else {
            *(float2*)(o + 0) = make_float2(v0 - l, v1 - l);
        }
    }
}

// ---------------- launch (single stream, graph-capture-safe) -----------------
extern "C" void kernel_launch(void* const* d_in, const int* in_sizes, int n_in,
                              void* d_out, int out_size) {
    const float* x   = (const float*)d_in[0];
    const void*  ei  = d_in[1];
    const float* w   = (const float*)d_in[2];
    const float* W1  = (const float*)d_in[3];
    const float* b1  = (const float*)d_in[4];
    const float* W2  = (const float*)d_in[5];
    const float* b2  = (const float*)d_in[6];
    float*       out = (float*)d_out;

    k_init      <<<(NN + 255) / 256, 256>>>(ei);
    k_deg_count <<<(EE / 4 + 255) / 256, 256>>>(ei, w);
    k_scan1     <<<NB1, SCAN_BLK>>>();
    k_scan23    <<<(NN + 255) / 256, 256>>>();
    k_scatter   <<<(EE + 255) / 256, 256>>>(ei, w);
    k_gemm1     <<<(NN + G1_ROWS - 1) / G1_ROWS, G1_THREADS>>>(x, W1);
    k_conv1f    <<<NN * 8 / 256, 256>>>(b1, W2);
    k_conv2f    <<<NN * 8 / 256, 256>>>(b2, out);
}